// round 16
// baseline (speedup 1.0000x reference)
#include <cuda_runtime.h>
#include <cuda_fp16.h>
#include <cstdint>

// Problem constants
static constexpr int O_DIM = 4096;     // out features (N)
static constexpr int I_DIM = 4096;     // in features (K)
static constexpr int M_DIM = 8 * 2048; // batch*seq (M)
static constexpr int R_DIM = 16;       // LoRA rank

// Scratch: fp16 operands (device globals — no allocation allowed)
__device__ __align__(16) __half g_Wq[(size_t)O_DIM * I_DIM];
__device__ __align__(16) __half g_Xq[(size_t)M_DIM * I_DIM];

// ---------------------------------------------------------------------------
// Fused prep kernel.
//   W path: 256 CTAs x 16 rows. Each thread caches its 4 `down` columns for
//   all 16 ranks in registers per 1024-col chunk -> down L2 traffic 1GB->64MB.
//   X path: fp32->fp16, 4 float4 per thread, streaming stores (unchanged).
// ---------------------------------------------------------------------------
static constexpr int ROWS_PER_CTA = 16;
static constexpr int NWBLK = O_DIM / ROWS_PER_CTA;   // 256 W-path blocks
static constexpr int XPT = 4;  // float4 elements per thread in x path
static constexpr int XBLK =
    (int)(((size_t)M_DIM * I_DIM / 4) / (256 * XPT));   // 16384 blocks

__global__ void prep_fused(const int* __restrict__ qw,
                           const float* __restrict__ scales,
                           const float* __restrict__ up,
                           const float* __restrict__ down,
                           const float* __restrict__ x) {
    const int tid = threadIdx.x;
    if (blockIdx.x < NWBLK) {
        // ---- W path: rows [o0, o0+16) ----
        const int o0 = blockIdx.x * ROWS_PER_CTA;
        __shared__ float upsm[ROWS_PER_CTA][R_DIM];
        // load up[o0..o0+16)[0..16) : 256 values, one per thread
        upsm[tid >> 4][tid & 15] = up[o0 * R_DIM + tid];
        __syncthreads();

#pragma unroll 1
        for (int c = 0; c < I_DIM / 1024; c++) {      // 4 chunks of 1024 cols
            const int col4 = c * 256 + tid;           // this thread's float4 col
            // cache down[r][col4] for all 16 ranks in registers
            float4 dreg[R_DIM];
#pragma unroll
            for (int r = 0; r < R_DIM; r++)
                dreg[r] = ((const float4*)(down + (size_t)r * I_DIM))[col4];

#pragma unroll 1
            for (int o = 0; o < ROWS_PER_CTA; o++) {
                const int orow = o0 + o;
                const int4 q = ((const int4*)(qw + (size_t)orow * I_DIM))[col4];
                const float sc = scales[orow * (I_DIM / 32) + (col4 >> 3)];
                float l0 = 0.f, l1 = 0.f, l2 = 0.f, l3 = 0.f;
#pragma unroll
                for (int r = 0; r < R_DIM; r++) {
                    const float u = upsm[o][r];
                    l0 = fmaf(u, dreg[r].x, l0); l1 = fmaf(u, dreg[r].y, l1);
                    l2 = fmaf(u, dreg[r].z, l2); l3 = fmaf(u, dreg[r].w, l3);
                }
                float w0 = fmaf(sc, (float)q.x - 128.f, 0.5f * l0);
                float w1 = fmaf(sc, (float)q.y - 128.f, 0.5f * l1);
                float w2 = fmaf(sc, (float)q.z - 128.f, 0.5f * l2);
                float w3 = fmaf(sc, (float)q.w - 128.f, 0.5f * l3);
                union { __half h[4]; uint2 u; } P;
                P.h[0] = __float2half_rn(w0); P.h[1] = __float2half_rn(w1);
                P.h[2] = __float2half_rn(w2); P.h[3] = __float2half_rn(w3);
                ((uint2*)g_Wq)[(size_t)orow * (I_DIM / 4) + col4] = P.u;
            }
        }
    } else {
        // ---- X path: 4 float4 (64B) -> 2 uint4 streaming stores (32B) ----
        const size_t t = (size_t)(blockIdx.x - NWBLK) * blockDim.x + tid;
        const size_t i4 = t * XPT;
#pragma unroll
        for (int h = 0; h < 2; h++) {
            const float4 v0 = ((const float4*)x)[i4 + 2 * h];
            const float4 v1 = ((const float4*)x)[i4 + 2 * h + 1];
            union { __half hh[8]; uint4 u; } P;
            P.hh[0] = __float2half_rn(v0.x); P.hh[1] = __float2half_rn(v0.y);
            P.hh[2] = __float2half_rn(v0.z); P.hh[3] = __float2half_rn(v0.w);
            P.hh[4] = __float2half_rn(v1.x); P.hh[5] = __float2half_rn(v1.y);
            P.hh[6] = __float2half_rn(v1.z); P.hh[7] = __float2half_rn(v1.w);
            __stcs((uint4*)g_Xq + t * 2 + h, P.u);
        }
    }
}

// ---------------------------------------------------------------------------
// GEMM  out[M][N] = Xq @ Wq^T + bias
// EXACT round-15 kernel (best known): persistent CTAs (2/SM), R9 mainloop,
// cross-tile pipeline carry-over.
// ---------------------------------------------------------------------------
static constexpr int BM = 128, BN = 128, BK = 32;
static constexpr int KT = I_DIM / BK;          // 128 K-tiles
static constexpr int NS = 4;                   // pipeline stages
static constexpr int TILE_BYTES = BM * 64;     // 8192 B per buffer (row = 64B)
static constexpr int STAGE_BYTES = 2 * TILE_BYTES;   // A, B
static constexpr int SMEM_BYTES = NS * STAGE_BYTES;  // 65536
static constexpr int NTHREADS = 128;
static constexpr int NTILES = (M_DIM / BM) * (O_DIM / BN);   // 4096
static constexpr int NGRID_X = O_DIM / BN;     // 32 (N fast within tile id)

__device__ __forceinline__ uint32_t cvta_smem(const void* p) {
    return (uint32_t)__cvta_generic_to_shared(p);
}
__device__ __forceinline__ void cp_async16(uint32_t s, const void* g) {
    asm volatile("cp.async.cg.shared.global [%0], [%1], 16;" :: "r"(s), "l"(g));
}
__device__ __forceinline__ void ldsm4(uint32_t (&r)[4], uint32_t addr) {
    asm volatile("ldmatrix.sync.aligned.m8n8.x4.shared.b16 {%0,%1,%2,%3}, [%4];"
                 : "=r"(r[0]), "=r"(r[1]), "=r"(r[2]), "=r"(r[3]) : "r"(addr));
}
__device__ __forceinline__ void mma16816(float (&d)[4], const uint32_t (&a)[4],
                                         uint32_t b0, uint32_t b1) {
    asm volatile(
        "mma.sync.aligned.m16n8k16.row.col.f32.f16.f16.f32 "
        "{%0,%1,%2,%3}, {%4,%5,%6,%7}, {%8,%9}, {%0,%1,%2,%3};"
        : "+f"(d[0]), "+f"(d[1]), "+f"(d[2]), "+f"(d[3])
        : "r"(a[0]), "r"(a[1]), "r"(a[2]), "r"(a[3]), "r"(b0), "r"(b1));
}

// Swizzle: 16B chunk c (0..3) in 64B row -> physical chunk c ^ ((row>>1)&3).
__device__ __forceinline__ uint32_t swz(int row, int c) {
    return (uint32_t)(row * 64 + ((c ^ ((row >> 1) & 3)) << 4));
}

__global__ __launch_bounds__(NTHREADS, 2)
void gemm_fp16(const float* __restrict__ bias, float* __restrict__ out) {
    extern __shared__ __align__(16) uint8_t smem[];
    const int tid  = threadIdx.x;
    const int lane = tid & 31;
    const int warp = tid >> 5;
    const int wm = warp >> 1;   // 0..1 (M)
    const int wn = warp & 1;    // 0..1 (N)

    const uint32_t sbase = cvta_smem(smem);

    // Loader geometry: 512 16B-chunks per buffer / 128 threads = 4 rows each.
    const int ldRow = tid >> 2;   // 0..31
    const int ldC   = tid & 3;
    uint32_t so[4];
    size_t gofs[4];
#pragma unroll
    for (int j = 0; j < 4; j++) {
        so[j] = swz(ldRow + 32 * j, ldC);
        gofs[j] = (size_t)(ldRow + 32 * j) * I_DIM + ldC * 8;
    }

    // Loop-invariant ldsm offsets (warp tile 64x64)
    uint32_t aoff[2][4], boff[2][4];
#pragma unroll
    for (int ks = 0; ks < 2; ks++) {
#pragma unroll
        for (int mt = 0; mt < 4; mt++)
            aoff[ks][mt] = swz(wm * 64 + mt * 16 + (lane & 15),
                               ks * 2 + (lane >> 4));
#pragma unroll
        for (int np = 0; np < 4; np++)
            boff[ks][np] = swz(wn * 64 + np * 16 + (lane & 7) + ((lane >> 4) << 3),
                               ks * 2 + ((lane >> 3) & 1));
    }

#define LOAD_ST(PA, PB, STG, K0) do {                                         \
        const uint32_t sb_ = sbase + (STG) * STAGE_BYTES;                     \
        _Pragma("unroll")                                                     \
        for (int j = 0; j < 4; j++) {                                         \
            cp_async16(sb_ + 0 * TILE_BYTES + so[j], (PA) + gofs[j] + (K0));  \
            cp_async16(sb_ + 1 * TILE_BYTES + so[j], (PB) + gofs[j] + (K0));  \
        }                                                                     \
        asm volatile("cp.async.commit_group;");                               \
    } while (0)

    int tile = blockIdx.x;
    int m0 = (tile >> 5) * BM;          // tile id: N fast (matches old grid)
    int n0 = (tile & (NGRID_X - 1)) * BN;
    const __half* aQ = g_Xq + (size_t)m0 * I_DIM;
    const __half* bQ = g_Wq + (size_t)n0 * I_DIM;

    // Prologue: stages 0..NS-2 of the first tile
#pragma unroll
    for (int t = 0; t < NS - 1; t++) LOAD_ST(aQ, bQ, t, (size_t)t * BK);

    float acc[4][8][4];

    for (;;) {
#pragma unroll
        for (int a = 0; a < 4; a++)
#pragma unroll
            for (int b = 0; b < 8; b++)
#pragma unroll
                for (int c = 0; c < 4; c++) acc[a][b][c] = 0.f;

        const int ntile = tile + (int)gridDim.x;
        const bool hasn = ntile < NTILES;
        const int mn0 = hasn ? (ntile >> 5) * BM : m0;
        const int nn0 = hasn ? (ntile & (NGRID_X - 1)) * BN : n0;
        const __half* aN = g_Xq + (size_t)mn0 * I_DIM;
        const __half* bN = g_Wq + (size_t)nn0 * I_DIM;

        for (int kt = 0; kt < KT; kt++) {
            asm volatile("cp.async.wait_group %0;" :: "n"(NS - 2));
            __syncthreads();
            const int T = kt + NS - 1;
            if (T < KT) {
                LOAD_ST(aQ, bQ, T & (NS - 1), (size_t)T * BK);
            } else if (hasn) {
                // tail: prologue of next tile, pipeline never drains
                LOAD_ST(aN, bN, T & (NS - 1), (size_t)(T - KT) * BK);
            } else {
                asm volatile("cp.async.commit_group;");
            }

            const uint32_t sb = sbase + (kt & (NS - 1)) * STAGE_BYTES;
            const uint32_t aB = sb + 0 * TILE_BYTES;
            const uint32_t bB = sb + 1 * TILE_BYTES;

#pragma unroll
            for (int ks = 0; ks < 2; ks++) {
                uint32_t af[4][4];
#pragma unroll
                for (int mt = 0; mt < 4; mt++) ldsm4(af[mt], aB + aoff[ks][mt]);
#pragma unroll
                for (int np = 0; np < 4; np++) {
                    uint32_t bf[4];
                    ldsm4(bf, bB + boff[ks][np]);
#pragma unroll
                    for (int mt = 0; mt < 4; mt++) {
                        mma16816(acc[mt][np * 2 + 0], af[mt], bf[0], bf[1]);
                        mma16816(acc[mt][np * 2 + 1], af[mt], bf[2], bf[3]);
                    }
                }
            }
        }

        // Epilogue (overlaps next tile's in-flight prologue loads)
#pragma unroll
        for (int mt = 0; mt < 4; mt++) {
#pragma unroll
            for (int nt = 0; nt < 8; nt++) {
                const int row = m0 + wm * 64 + mt * 16 + (lane >> 2);
                const int col = n0 + wn * 64 + nt * 8 + (lane & 3) * 2;
                const float b0 = bias[col], b1 = bias[col + 1];
                float2 v0 = {acc[mt][nt][0] + b0, acc[mt][nt][1] + b1};
                float2 v1 = {acc[mt][nt][2] + b0, acc[mt][nt][3] + b1};
                __stcs((float2*)(out + (size_t)row * O_DIM + col), v0);
                __stcs((float2*)(out + (size_t)(row + 8) * O_DIM + col), v1);
            }
        }

        if (!hasn) break;
        tile = ntile; m0 = mn0; n0 = nn0; aQ = aN; bQ = bN;
    }
#undef LOAD_ST
}

// ---------------------------------------------------------------------------
extern "C" void kernel_launch(void* const* d_in, const int* in_sizes, int n_in,
                              void* d_out, int out_size) {
    const int*   qweight   = (const int*)d_in[0];
    const float* scales    = (const float*)d_in[1];
    const float* lora_up   = (const float*)d_in[2];
    const float* lora_down = (const float*)d_in[3];
    const float* bias      = (const float*)d_in[4];
    const float* x         = (const float*)d_in[5];
    float* out = (float*)d_out;

    prep_fused<<<NWBLK + XBLK, 256>>>(qweight, scales, lora_up, lora_down, x);

    int dev = 0, nsm = 148;
    cudaGetDevice(&dev);
    cudaDeviceGetAttribute(&nsm, cudaDevAttrMultiProcessorCount, dev);

    cudaFuncSetAttribute(gemm_fp16,
                         cudaFuncAttributeMaxDynamicSharedMemorySize, SMEM_BYTES);
    gemm_fp16<<<2 * nsm, NTHREADS, SMEM_BYTES>>>(bias, out);
}

// round 17
// speedup vs baseline: 1.0073x; 1.0073x over previous
#include <cuda_runtime.h>
#include <cuda_fp16.h>
#include <cstdint>

// Problem constants
static constexpr int O_DIM = 4096;     // out features (N)
static constexpr int I_DIM = 4096;     // in features (K)
static constexpr int M_DIM = 8 * 2048; // batch*seq (M)
static constexpr int R_DIM = 16;       // LoRA rank

// Scratch: fp16 operands (device globals — no allocation allowed)
__device__ __align__(16) __half g_Wq[(size_t)O_DIM * I_DIM];
__device__ __align__(16) __half g_Xq[(size_t)M_DIM * I_DIM];

// ---------------------------------------------------------------------------
// Fused prep kernel (R15-proven paths; X blocks scheduled FIRST so the
// DRAM-bound X conversion saturates memory from wave 0, W rows backfill).
// ---------------------------------------------------------------------------
static constexpr int XPT = 4;  // float4 elements per thread in x path
static constexpr int XBLK =
    (int)(((size_t)M_DIM * I_DIM / 4) / (256 * XPT));   // 16384 blocks

__global__ void prep_fused(const int* __restrict__ qw,
                           const float* __restrict__ scales,
                           const float* __restrict__ up,
                           const float* __restrict__ down,
                           const float* __restrict__ x) {
    const int tid = threadIdx.x;
    if (blockIdx.x < XBLK) {
        // ---- X path: 4 float4 (64B) -> 2 uint4 streaming stores (32B) ----
        const size_t t = (size_t)blockIdx.x * blockDim.x + tid;
        const size_t i4 = t * XPT;
#pragma unroll
        for (int h = 0; h < 2; h++) {
            const float4 v0 = ((const float4*)x)[i4 + 2 * h];
            const float4 v1 = ((const float4*)x)[i4 + 2 * h + 1];
            union { __half hh[8]; uint4 u; } P;
            P.hh[0] = __float2half_rn(v0.x); P.hh[1] = __float2half_rn(v0.y);
            P.hh[2] = __float2half_rn(v0.z); P.hh[3] = __float2half_rn(v0.w);
            P.hh[4] = __float2half_rn(v1.x); P.hh[5] = __float2half_rn(v1.y);
            P.hh[6] = __float2half_rn(v1.z); P.hh[7] = __float2half_rn(v1.w);
            __stcs((uint4*)g_Xq + t * 2 + h, P.u);
        }
    } else {
        // ---- W path: one output row per block (R15-proven) ----
        const int o = blockIdx.x - XBLK;
        __shared__ float up_s[R_DIM];
        if (tid < R_DIM) up_s[tid] = up[o * R_DIM + tid];
        __syncthreads();

        const int4* qrow = (const int4*)(qw + (size_t)o * I_DIM);
        for (int i = tid; i < I_DIM / 4; i += blockDim.x) {
            const int4 q = qrow[i];
            const float sc = scales[o * (I_DIM / 32) + (i >> 3)];
            float l[4] = {0.f, 0.f, 0.f, 0.f};
#pragma unroll
            for (int r = 0; r < R_DIM; r++) {
                const float4 d4 = ((const float4*)(down + (size_t)r * I_DIM))[i];
                const float u = up_s[r];
                l[0] = fmaf(u, d4.x, l[0]); l[1] = fmaf(u, d4.y, l[1]);
                l[2] = fmaf(u, d4.z, l[2]); l[3] = fmaf(u, d4.w, l[3]);
            }
            float w[4];
            w[0] = fmaf(sc, (float)q.x - 128.f, 0.5f * l[0]);
            w[1] = fmaf(sc, (float)q.y - 128.f, 0.5f * l[1]);
            w[2] = fmaf(sc, (float)q.z - 128.f, 0.5f * l[2]);
            w[3] = fmaf(sc, (float)q.w - 128.f, 0.5f * l[3]);
            union { __half h[4]; uint2 u; } P;
#pragma unroll
            for (int j = 0; j < 4; j++) P.h[j] = __float2half_rn(w[j]);
            ((uint2*)g_Wq)[(size_t)o * (I_DIM / 4) + i] = P.u;
        }
    }
}

// ---------------------------------------------------------------------------
// GEMM  out[M][N] = Xq @ Wq^T + bias
// EXACT round-15 kernel (best known: 1143.6us, tensor 86.3%): persistent
// CTAs (2/SM), R9 mainloop, cross-tile pipeline carry-over.
// ---------------------------------------------------------------------------
static constexpr int BM = 128, BN = 128, BK = 32;
static constexpr int KT = I_DIM / BK;          // 128 K-tiles
static constexpr int NS = 4;                   // pipeline stages
static constexpr int TILE_BYTES = BM * 64;     // 8192 B per buffer (row = 64B)
static constexpr int STAGE_BYTES = 2 * TILE_BYTES;   // A, B
static constexpr int SMEM_BYTES = NS * STAGE_BYTES;  // 65536
static constexpr int NTHREADS = 128;
static constexpr int NTILES = (M_DIM / BM) * (O_DIM / BN);   // 4096
static constexpr int NGRID_X = O_DIM / BN;     // 32 (N fast within tile id)

__device__ __forceinline__ uint32_t cvta_smem(const void* p) {
    return (uint32_t)__cvta_generic_to_shared(p);
}
__device__ __forceinline__ void cp_async16(uint32_t s, const void* g) {
    asm volatile("cp.async.cg.shared.global [%0], [%1], 16;" :: "r"(s), "l"(g));
}
__device__ __forceinline__ void ldsm4(uint32_t (&r)[4], uint32_t addr) {
    asm volatile("ldmatrix.sync.aligned.m8n8.x4.shared.b16 {%0,%1,%2,%3}, [%4];"
                 : "=r"(r[0]), "=r"(r[1]), "=r"(r[2]), "=r"(r[3]) : "r"(addr));
}
__device__ __forceinline__ void mma16816(float (&d)[4], const uint32_t (&a)[4],
                                         uint32_t b0, uint32_t b1) {
    asm volatile(
        "mma.sync.aligned.m16n8k16.row.col.f32.f16.f16.f32 "
        "{%0,%1,%2,%3}, {%4,%5,%6,%7}, {%8,%9}, {%0,%1,%2,%3};"
        : "+f"(d[0]), "+f"(d[1]), "+f"(d[2]), "+f"(d[3])
        : "r"(a[0]), "r"(a[1]), "r"(a[2]), "r"(a[3]), "r"(b0), "r"(b1));
}

// Swizzle: 16B chunk c (0..3) in 64B row -> physical chunk c ^ ((row>>1)&3).
__device__ __forceinline__ uint32_t swz(int row, int c) {
    return (uint32_t)(row * 64 + ((c ^ ((row >> 1) & 3)) << 4));
}

__global__ __launch_bounds__(NTHREADS, 2)
void gemm_fp16(const float* __restrict__ bias, float* __restrict__ out) {
    extern __shared__ __align__(16) uint8_t smem[];
    const int tid  = threadIdx.x;
    const int lane = tid & 31;
    const int warp = tid >> 5;
    const int wm = warp >> 1;   // 0..1 (M)
    const int wn = warp & 1;    // 0..1 (N)

    const uint32_t sbase = cvta_smem(smem);

    // Loader geometry: 512 16B-chunks per buffer / 128 threads = 4 rows each.
    const int ldRow = tid >> 2;   // 0..31
    const int ldC   = tid & 3;
    uint32_t so[4];
    size_t gofs[4];
#pragma unroll
    for (int j = 0; j < 4; j++) {
        so[j] = swz(ldRow + 32 * j, ldC);
        gofs[j] = (size_t)(ldRow + 32 * j) * I_DIM + ldC * 8;
    }

    // Loop-invariant ldsm offsets (warp tile 64x64)
    uint32_t aoff[2][4], boff[2][4];
#pragma unroll
    for (int ks = 0; ks < 2; ks++) {
#pragma unroll
        for (int mt = 0; mt < 4; mt++)
            aoff[ks][mt] = swz(wm * 64 + mt * 16 + (lane & 15),
                               ks * 2 + (lane >> 4));
#pragma unroll
        for (int np = 0; np < 4; np++)
            boff[ks][np] = swz(wn * 64 + np * 16 + (lane & 7) + ((lane >> 4) << 3),
                               ks * 2 + ((lane >> 3) & 1));
    }

#define LOAD_ST(PA, PB, STG, K0) do {                                         \
        const uint32_t sb_ = sbase + (STG) * STAGE_BYTES;                     \
        _Pragma("unroll")                                                     \
        for (int j = 0; j < 4; j++) {                                         \
            cp_async16(sb_ + 0 * TILE_BYTES + so[j], (PA) + gofs[j] + (K0));  \
            cp_async16(sb_ + 1 * TILE_BYTES + so[j], (PB) + gofs[j] + (K0));  \
        }                                                                     \
        asm volatile("cp.async.commit_group;");                               \
    } while (0)

    int tile = blockIdx.x;
    int m0 = (tile >> 5) * BM;          // tile id: N fast (matches old grid)
    int n0 = (tile & (NGRID_X - 1)) * BN;
    const __half* aQ = g_Xq + (size_t)m0 * I_DIM;
    const __half* bQ = g_Wq + (size_t)n0 * I_DIM;

    // Prologue: stages 0..NS-2 of the first tile
#pragma unroll
    for (int t = 0; t < NS - 1; t++) LOAD_ST(aQ, bQ, t, (size_t)t * BK);

    float acc[4][8][4];

    for (;;) {
#pragma unroll
        for (int a = 0; a < 4; a++)
#pragma unroll
            for (int b = 0; b < 8; b++)
#pragma unroll
                for (int c = 0; c < 4; c++) acc[a][b][c] = 0.f;

        const int ntile = tile + (int)gridDim.x;
        const bool hasn = ntile < NTILES;
        const int mn0 = hasn ? (ntile >> 5) * BM : m0;
        const int nn0 = hasn ? (ntile & (NGRID_X - 1)) * BN : n0;
        const __half* aN = g_Xq + (size_t)mn0 * I_DIM;
        const __half* bN = g_Wq + (size_t)nn0 * I_DIM;

        for (int kt = 0; kt < KT; kt++) {
            asm volatile("cp.async.wait_group %0;" :: "n"(NS - 2));
            __syncthreads();
            const int T = kt + NS - 1;
            if (T < KT) {
                LOAD_ST(aQ, bQ, T & (NS - 1), (size_t)T * BK);
            } else if (hasn) {
                // tail: prologue of next tile, pipeline never drains
                LOAD_ST(aN, bN, T & (NS - 1), (size_t)(T - KT) * BK);
            } else {
                asm volatile("cp.async.commit_group;");
            }

            const uint32_t sb = sbase + (kt & (NS - 1)) * STAGE_BYTES;
            const uint32_t aB = sb + 0 * TILE_BYTES;
            const uint32_t bB = sb + 1 * TILE_BYTES;

#pragma unroll
            for (int ks = 0; ks < 2; ks++) {
                uint32_t af[4][4];
#pragma unroll
                for (int mt = 0; mt < 4; mt++) ldsm4(af[mt], aB + aoff[ks][mt]);
#pragma unroll
                for (int np = 0; np < 4; np++) {
                    uint32_t bf[4];
                    ldsm4(bf, bB + boff[ks][np]);
#pragma unroll
                    for (int mt = 0; mt < 4; mt++) {
                        mma16816(acc[mt][np * 2 + 0], af[mt], bf[0], bf[1]);
                        mma16816(acc[mt][np * 2 + 1], af[mt], bf[2], bf[3]);
                    }
                }
            }
        }

        // Epilogue (overlaps next tile's in-flight prologue loads)
#pragma unroll
        for (int mt = 0; mt < 4; mt++) {
#pragma unroll
            for (int nt = 0; nt < 8; nt++) {
                const int row = m0 + wm * 64 + mt * 16 + (lane >> 2);
                const int col = n0 + wn * 64 + nt * 8 + (lane & 3) * 2;
                const float b0 = bias[col], b1 = bias[col + 1];
                float2 v0 = {acc[mt][nt][0] + b0, acc[mt][nt][1] + b1};
                float2 v1 = {acc[mt][nt][2] + b0, acc[mt][nt][3] + b1};
                __stcs((float2*)(out + (size_t)row * O_DIM + col), v0);
                __stcs((float2*)(out + (size_t)(row + 8) * O_DIM + col), v1);
            }
        }

        if (!hasn) break;
        tile = ntile; m0 = mn0; n0 = nn0; aQ = aN; bQ = bN;
    }
#undef LOAD_ST
}

// ---------------------------------------------------------------------------
extern "C" void kernel_launch(void* const* d_in, const int* in_sizes, int n_in,
                              void* d_out, int out_size) {
    const int*   qweight   = (const int*)d_in[0];
    const float* scales    = (const float*)d_in[1];
    const float* lora_up   = (const float*)d_in[2];
    const float* lora_down = (const float*)d_in[3];
    const float* bias      = (const float*)d_in[4];
    const float* x         = (const float*)d_in[5];
    float* out = (float*)d_out;

    prep_fused<<<XBLK + O_DIM, 256>>>(qweight, scales, lora_up, lora_down, x);

    int dev = 0, nsm = 148;
    cudaGetDevice(&dev);
    cudaDeviceGetAttribute(&nsm, cudaDevAttrMultiProcessorCount, dev);

    cudaFuncSetAttribute(gemm_fp16,
                         cudaFuncAttributeMaxDynamicSharedMemorySize, SMEM_BYTES);
    gemm_fp16<<<2 * nsm, NTHREADS, SMEM_BYTES>>>(bias, out);
}